// round 1
// baseline (speedup 1.0000x reference)
#include <cuda_runtime.h>
#include <math.h>

#define HW   61440
#define TILE 64
#define LDA  260   // activation row stride (floats), 16B-aligned, avoids pathological conflicts
#define LDW  257   // transposed weight buffer row stride: 257 % 32 == 1 -> conflict-free

// Layer GEMM: Aout[64xN] = f(Ain[64xK] @ W^T + bias)
// Threads (32,8): thread (tx,ty) computes rows ty*8..ty*8+7, cols tx+32*c.
// A reads are warp-broadcast, W reads are stride-1 from transposed smem chunk.
template<int K, int N, bool SIN, bool L0>
__device__ __forceinline__ void layer_gemm(
    const float* __restrict__ Ain, float* __restrict__ Aout,
    const float* __restrict__ W, int ldw,
    const float* __restrict__ bias,
    const float* __restrict__ wt, float tval,
    float* __restrict__ Wb,
    int tx, int ty, int tid)
{
    constexpr int CPT = N / 32;   // cols per thread
    float acc[8][CPT];
    #pragma unroll
    for (int i = 0; i < 8; ++i)
        #pragma unroll
        for (int c = 0; c < CPT; ++c) acc[i][c] = 0.0f;

    const int rbase = ty * 8;

    for (int kc = 0; kc < K; kc += 64) {
        // Stage W chunk [N][64] -> Wb[64][N] (transposed).
        // Consecutive tid -> consecutive k: coalesced global reads.
        // Smem stores stride LDW=257 -> consecutive banks.
        for (int e = tid; e < N * 64; e += 256) {
            int k = e & 63, n = e >> 6;
            Wb[k * LDW + n] = W[n * ldw + kc + k];
        }
        __syncthreads();

        #pragma unroll 4
        for (int k = 0; k < 64; ++k) {
            float a[8];
            #pragma unroll
            for (int i = 0; i < 8; ++i)
                a[i] = Ain[(rbase + i) * LDA + kc + k];   // broadcast within warp
            #pragma unroll
            for (int c = 0; c < CPT; ++c) {
                float w = Wb[k * LDW + tx + 32 * c];       // stride-1, no conflicts
                #pragma unroll
                for (int i = 0; i < 8; ++i)
                    acc[i][c] = fmaf(a[i], w, acc[i][c]);
            }
        }
        __syncthreads();
    }

    // Epilogue: bias (+ folded time term for layer 0), sin(30x) for hidden layers.
    #pragma unroll
    for (int c = 0; c < CPT; ++c) {
        int col = tx + 32 * c;
        float bb = bias[col];
        if constexpr (L0) bb += tval * wt[col * 65];   // W0[col][64] * t
        #pragma unroll
        for (int i = 0; i < 8; ++i) {
            float v = acc[i][c] + bb;
            if constexpr (SIN) v = sinf(30.0f * v);
            Aout[(rbase + i) * LDA + col] = v;
        }
    }
    __syncthreads();
}

extern __shared__ float smem[];

__global__ __launch_bounds__(256, 1)
void liif_siren_kernel(
    const float* __restrict__ feat, const float* __restrict__ times,
    const float* __restrict__ w0, const float* __restrict__ b0,
    const float* __restrict__ w1, const float* __restrict__ b1,
    const float* __restrict__ w2, const float* __restrict__ b2,
    const float* __restrict__ w3, const float* __restrict__ b3,
    const float* __restrict__ w4, const float* __restrict__ b4,
    const float* __restrict__ w5, const float* __restrict__ b5,
    float* __restrict__ out)
{
    float* A0 = smem;                 // 64 x LDA
    float* A1 = A0 + TILE * LDA;      // 64 x LDA
    float* Wb = A1 + TILE * LDA;      // 64 x LDW

    const int tx = threadIdx.x, ty = threadIdx.y;
    const int tid = ty * 32 + tx;
    const int p0 = blockIdx.x * TILE;   // pixel tile start
    const int b  = blockIdx.y;          // batch
    const int t  = blockIdx.z;          // time index
    const float tval = times[t];

    // Gather is identity: A0[p][c] = feat[b][c][p0+p]. Coalesced (64-float runs).
    for (int e = tid; e < TILE * 64; e += 256) {
        int p = e & 63, c = e >> 6;
        A0[p * LDA + c] = feat[(b * 64 + c) * HW + p0 + p];
    }
    __syncthreads();

    // L0: 65->64 (time folded into bias), L1: 64->64, L2: 64->256,
    // L3/L4: 256->256, L5: 256->64 linear.
    layer_gemm< 64,  64, true,  true >(A0, A1, w0, 65,  b0, w0 + 64, tval, Wb, tx, ty, tid);
    layer_gemm< 64,  64, true,  false>(A1, A0, w1, 64,  b1, nullptr, 0.f,  Wb, tx, ty, tid);
    layer_gemm< 64, 256, true,  false>(A0, A1, w2, 64,  b2, nullptr, 0.f,  Wb, tx, ty, tid);
    layer_gemm<256, 256, true,  false>(A1, A0, w3, 256, b3, nullptr, 0.f,  Wb, tx, ty, tid);
    layer_gemm<256, 256, true,  false>(A0, A1, w4, 256, b4, nullptr, 0.f,  Wb, tx, ty, tid);
    layer_gemm<256,  64, false, false>(A1, A0, w5, 256, b5, nullptr, 0.f,  Wb, tx, ty, tid);

    // out[t][b][o][p0+p]
    for (int e = tid; e < TILE * 64; e += 256) {
        int p = e & 63, o = e >> 6;
        out[(size_t)((t * 2 + b) * 64 + o) * HW + p0 + p] = A0[p * LDA + o];
    }
}

extern "C" void kernel_launch(void* const* d_in, const int* in_sizes, int n_in,
                              void* d_out, int out_size) {
    const float* feat  = (const float*)d_in[0];
    const float* times = (const float*)d_in[1];
    const float* w0 = (const float*)d_in[2];
    const float* b0 = (const float*)d_in[3];
    const float* w1 = (const float*)d_in[4];
    const float* b1 = (const float*)d_in[5];
    const float* w2 = (const float*)d_in[6];
    const float* b2 = (const float*)d_in[7];
    const float* w3 = (const float*)d_in[8];
    const float* b3 = (const float*)d_in[9];
    const float* w4 = (const float*)d_in[10];
    const float* b4 = (const float*)d_in[11];
    const float* w5 = (const float*)d_in[12];
    const float* b5 = (const float*)d_in[13];
    float* out = (float*)d_out;

    const size_t smem_bytes = (size_t)(2 * TILE * LDA + 64 * LDW) * sizeof(float); // 198912
    cudaFuncSetAttribute(liif_siren_kernel,
                         cudaFuncAttributeMaxDynamicSharedMemorySize, (int)smem_bytes);

    dim3 grid(HW / TILE, 2, 3);   // 960 x 2 x 3 = 5760 blocks
    dim3 block(32, 8, 1);
    liif_siren_kernel<<<grid, block, smem_bytes>>>(
        feat, times, w0, b0, w1, b1, w2, b2, w3, b3, w4, b4, w5, b5, out);
}

// round 2
// speedup vs baseline: 1.0680x; 1.0680x over previous
#include <cuda_runtime.h>
#include <math.h>

#define HW   61440
#define TILE 64
#define LDA  66    // transposed activation stride: [feat][pixel], 66 = even (8B pairs) & 2-way-conflict max
#define LDW  257   // transposed weight buffer row stride: 257 % 32 == 1 -> conflict-free

typedef unsigned long long u64;

__device__ __forceinline__ u64 pack_dup(float w) {
    u64 r; asm("mov.b64 %0, {%1,%2};" : "=l"(r) : "f"(w), "f"(w)); return r;
}
__device__ __forceinline__ void ffma2(u64 &d, u64 a, u64 b) {
    asm("fma.rn.f32x2 %0, %1, %2, %0;" : "+l"(d) : "l"(a), "l"(b));
}
__device__ __forceinline__ void unpack2(u64 v, float &lo, float &hi) {
    asm("mov.b64 {%0,%1}, %2;" : "=f"(lo), "=f"(hi) : "l"(v));
}

// Layer: Aout^T[N][64] = f(W[NxK] @ Ain^T[K][64] + bias)
// A buffers are TRANSPOSED: [feature][pixel], stride LDA.
// Threads (32,8): thread (tx,ty) owns pixel rows ty*8..ty*8+7 (as 4 f32x2 pairs),
// cols tx+32*c. a-loads: broadcast LDS.64. w-loads: stride-1 LDS.32 + dup-pack.
template<int K, int N, bool SIN, bool L0>
__device__ __forceinline__ void layer_gemm(
    const float* __restrict__ Ain, float* __restrict__ Aout,
    const float* __restrict__ W, int ldw,
    const float* __restrict__ bias,
    const float* __restrict__ wt, float tval,
    float* __restrict__ Wb,
    int tx, int ty, int tid)
{
    constexpr int CPT = N / 32;   // cols per thread
    u64 acc[4][CPT];
    #pragma unroll
    for (int i = 0; i < 4; ++i)
        #pragma unroll
        for (int c = 0; c < CPT; ++c) acc[i][c] = 0ULL;

    const int rbase = ty * 8;

    for (int kc = 0; kc < K; kc += 64) {
        // Stage W chunk [N][64] -> Wb[64][N] transposed.
        // lanes -> consecutive k: coalesced global; smem stride LDW -> conflict-free.
        for (int e = tid; e < N * 64; e += 256) {
            int k = e & 63, n = e >> 6;
            Wb[k * LDW + n] = W[n * ldw + kc + k];
        }
        __syncthreads();

        #pragma unroll 4
        for (int k = 0; k < 64; ++k) {
            const float* arow = Ain + (kc + k) * LDA + rbase;
            u64 a2[4];
            #pragma unroll
            for (int i = 0; i < 4; ++i)
                a2[i] = *(const u64*)(arow + 2 * i);      // broadcast LDS.64
            #pragma unroll
            for (int c = 0; c < CPT; ++c) {
                u64 w2 = pack_dup(Wb[k * LDW + tx + 32 * c]);
                #pragma unroll
                for (int i = 0; i < 4; ++i)
                    ffma2(acc[i][c], a2[i], w2);
            }
        }
        __syncthreads();
    }

    // Epilogue: bias (+ folded time for layer 0), sin(30x) on hidden layers.
    #pragma unroll
    for (int c = 0; c < CPT; ++c) {
        int col = tx + 32 * c;
        float bb = bias[col];
        if constexpr (L0) bb += tval * wt[col * 65];   // W0[col][64] * t
        #pragma unroll
        for (int i = 0; i < 4; ++i) {
            float lo, hi;
            unpack2(acc[i][c], lo, hi);
            lo += bb; hi += bb;
            if constexpr (SIN) { lo = sinf(30.0f * lo); hi = sinf(30.0f * hi); }
            float2 v = make_float2(lo, hi);
            *(float2*)(Aout + col * LDA + rbase + 2 * i) = v;  // ~2-way conflict
        }
    }
    __syncthreads();
}

extern __shared__ float smem[];

__global__ __launch_bounds__(256, 1)
void liif_siren_kernel(
    const float* __restrict__ feat, const float* __restrict__ times,
    const float* __restrict__ w0, const float* __restrict__ b0,
    const float* __restrict__ w1, const float* __restrict__ b1,
    const float* __restrict__ w2, const float* __restrict__ b2,
    const float* __restrict__ w3, const float* __restrict__ b3,
    const float* __restrict__ w4, const float* __restrict__ b4,
    const float* __restrict__ w5, const float* __restrict__ b5,
    float* __restrict__ out)
{
    float* A0 = smem;                 // 256 x LDA (transposed: [feat][pixel])
    float* A1 = A0 + 256 * LDA;       // 256 x LDA
    float* Wb = A1 + 256 * LDA;       // 64 x LDW

    const int tx = threadIdx.x, ty = threadIdx.y;
    const int tid = ty * 32 + tx;
    const int p0 = blockIdx.x * TILE;   // pixel tile start
    const int b  = blockIdx.y;          // batch
    const int t  = blockIdx.z;          // time index
    const float tval = times[t];

    // Identity gather, transposed store: A0[c][p] = feat[b][c][p0+p].
    for (int e = tid; e < TILE * 64; e += 256) {
        int p = e & 63, c = e >> 6;
        A0[c * LDA + p] = feat[(b * 64 + c) * HW + p0 + p];
    }
    __syncthreads();

    layer_gemm< 64,  64, true,  true >(A0, A1, w0, 65,  b0, w0 + 64, tval, Wb, tx, ty, tid);
    layer_gemm< 64,  64, true,  false>(A1, A0, w1, 64,  b1, nullptr, 0.f,  Wb, tx, ty, tid);
    layer_gemm< 64, 256, true,  false>(A0, A1, w2, 64,  b2, nullptr, 0.f,  Wb, tx, ty, tid);
    layer_gemm<256, 256, true,  false>(A1, A0, w3, 256, b3, nullptr, 0.f,  Wb, tx, ty, tid);
    layer_gemm<256, 256, true,  false>(A0, A1, w4, 256, b4, nullptr, 0.f,  Wb, tx, ty, tid);
    layer_gemm<256,  64, false, false>(A1, A0, w5, 256, b5, nullptr, 0.f,  Wb, tx, ty, tid);

    // out[t][b][o][p0+p], result in A0 as [o][p].
    for (int e = tid; e < TILE * 64; e += 256) {
        int p = e & 63, o = e >> 6;
        out[(size_t)((t * 2 + b) * 64 + o) * HW + p0 + p] = A0[o * LDA + p];
    }
}

extern "C" void kernel_launch(void* const* d_in, const int* in_sizes, int n_in,
                              void* d_out, int out_size) {
    const float* feat  = (const float*)d_in[0];
    const float* times = (const float*)d_in[1];
    const float* w0 = (const float*)d_in[2];
    const float* b0 = (const float*)d_in[3];
    const float* w1 = (const float*)d_in[4];
    const float* b1 = (const float*)d_in[5];
    const float* w2 = (const float*)d_in[6];
    const float* b2 = (const float*)d_in[7];
    const float* w3 = (const float*)d_in[8];
    const float* b3 = (const float*)d_in[9];
    const float* w4 = (const float*)d_in[10];
    const float* b4 = (const float*)d_in[11];
    const float* w5 = (const float*)d_in[12];
    const float* b5 = (const float*)d_in[13];
    float* out = (float*)d_out;

    const size_t smem_bytes = (size_t)(2 * 256 * LDA + 64 * LDW) * sizeof(float); // 200960 B
    cudaFuncSetAttribute(liif_siren_kernel,
                         cudaFuncAttributeMaxDynamicSharedMemorySize, (int)smem_bytes);

    dim3 grid(HW / TILE, 2, 3);   // 960 x 2 x 3 = 5760 blocks
    dim3 block(32, 8, 1);
    liif_siren_kernel<<<grid, block, smem_bytes>>>(
        feat, times, w0, b0, w1, b1, w2, b2, w3, b3, w4, b4, w5, b5, out);
}

// round 4
// speedup vs baseline: 1.4102x; 1.3204x over previous
#include <cuda_runtime.h>
#include <math.h>

#define HW   61440
#define TILE 64
#define LDA  66    // transposed activation stride [feat][pixel]; even (8B pairs), 2-way conflict max
#define LDW  257   // transposed weight buffer stride: 257 % 32 == 1 -> conflict-free
#define NTHR 512

typedef unsigned long long u64;

__device__ __forceinline__ u64 pack_dup(float w) {
    u64 r; asm("mov.b64 %0, {%1,%2};" : "=l"(r) : "f"(w), "f"(w)); return r;
}
__device__ __forceinline__ void ffma2(u64 &d, u64 a, u64 b) {
    asm("fma.rn.f32x2 %0, %1, %2, %0;" : "+l"(d) : "l"(a), "l"(b));
}
__device__ __forceinline__ void unpack2(u64 v, float &lo, float &hi) {
    asm("mov.b64 {%0,%1}, %2;" : "=f"(lo), "=f"(hi) : "l"(v));
}

// Layer: Aout^T[N][64] = f(W[NxK] @ Ain^T[K][64] + bias)
// A buffers TRANSPOSED: [feature][pixel], stride LDA.
// Block (32,16): rg=ty&7 -> pixel rows rg*8..rg*8+7 (4 f32x2 pairs),
//                cg=ty>>3 -> column half; cols = tx + 32*(cg*CPT + c), CPT=N/64.
template<int K, int N, bool SIN, bool L0>
__device__ __forceinline__ void layer_gemm(
    const float* __restrict__ Ain, float* __restrict__ Aout,
    const float* __restrict__ W, int ldw,
    const float* __restrict__ bias,
    const float* __restrict__ wt, float tval,
    float* __restrict__ Wb,
    int tx, int ty, int tid)
{
    constexpr int CPT = N / 64;   // cols per thread (1 or 4)
    u64 acc[4][CPT];
    #pragma unroll
    for (int i = 0; i < 4; ++i)
        #pragma unroll
        for (int c = 0; c < CPT; ++c) acc[i][c] = 0ULL;

    const int rbase = (ty & 7) * 8;
    const int cg    = ty >> 3;
    const int cbase = tx + 32 * (cg * CPT);

    for (int kc = 0; kc < K; kc += 64) {
        // Stage W chunk [N][64] -> Wb[64][N] transposed. Coalesced global reads,
        // conflict-free smem writes (stride LDW).
        for (int e = tid; e < N * 64; e += NTHR) {
            int k = e & 63, n = e >> 6;
            Wb[k * LDW + n] = W[n * ldw + kc + k];
        }
        __syncthreads();

        #pragma unroll 4
        for (int k = 0; k < 64; ++k) {
            const float* arow = Ain + (kc + k) * LDA + rbase;
            u64 a2[4];
            #pragma unroll
            for (int i = 0; i < 4; ++i)
                a2[i] = *(const u64*)(arow + 2 * i);      // broadcast LDS.64
            #pragma unroll
            for (int c = 0; c < CPT; ++c) {
                u64 w2 = pack_dup(Wb[k * LDW + cbase + 32 * c]);  // stride-1 LDS.32
                #pragma unroll
                for (int i = 0; i < 4; ++i)
                    ffma2(acc[i][c], a2[i], w2);
            }
        }
        __syncthreads();
    }

    // Epilogue: bias (+ folded time for layer 0), sin(30x) on hidden layers.
    #pragma unroll
    for (int c = 0; c < CPT; ++c) {
        int col = cbase + 32 * c;
        float bb = bias[col];
        if constexpr (L0) bb += tval * wt[col * 65];   // W0[col][64] * t
        #pragma unroll
        for (int i = 0; i < 4; ++i) {
            float lo, hi;
            unpack2(acc[i][c], lo, hi);
            lo += bb; hi += bb;
            if constexpr (SIN) { lo = sinf(30.0f * lo); hi = sinf(30.0f * hi); }
            float2 v = make_float2(lo, hi);
            *(float2*)(Aout + col * LDA + rbase + 2 * i) = v;  // ~2-way conflict
        }
    }
    __syncthreads();
}

extern __shared__ float smem[];

__global__ __launch_bounds__(NTHR, 1)
void liif_siren_kernel(
    const float* __restrict__ feat, const float* __restrict__ times,
    const float* __restrict__ w0, const float* __restrict__ b0,
    const float* __restrict__ w1, const float* __restrict__ b1,
    const float* __restrict__ w2, const float* __restrict__ b2,
    const float* __restrict__ w3, const float* __restrict__ b3,
    const float* __restrict__ w4, const float* __restrict__ b4,
    const float* __restrict__ w5, const float* __restrict__ b5,
    float* __restrict__ out)
{
    float* A0 = smem;                 // 256 x LDA ([feat][pixel])
    float* A1 = A0 + 256 * LDA;       // 256 x LDA
    float* Wb = A1 + 256 * LDA;       // 64 x LDW

    const int tx = threadIdx.x, ty = threadIdx.y;
    const int tid = ty * 32 + tx;
    const int p0 = blockIdx.x * TILE;
    const int b  = blockIdx.y;
    const int t  = blockIdx.z;
    const float tval = times[t];

    // Identity gather, transposed store: A0[c][p] = feat[b][c][p0+p].
    for (int e = tid; e < TILE * 64; e += NTHR) {
        int p = e & 63, c = e >> 6;
        A0[c * LDA + p] = feat[(b * 64 + c) * HW + p0 + p];
    }
    __syncthreads();

    layer_gemm< 64,  64, true,  true >(A0, A1, w0, 65,  b0, w0 + 64, tval, Wb, tx, ty, tid);
    layer_gemm< 64,  64, true,  false>(A1, A0, w1, 64,  b1, nullptr, 0.f,  Wb, tx, ty, tid);
    layer_gemm< 64, 256, true,  false>(A0, A1, w2, 64,  b2, nullptr, 0.f,  Wb, tx, ty, tid);
    layer_gemm<256, 256, true,  false>(A1, A0, w3, 256, b3, nullptr, 0.f,  Wb, tx, ty, tid);
    layer_gemm<256, 256, true,  false>(A0, A1, w4, 256, b4, nullptr, 0.f,  Wb, tx, ty, tid);
    layer_gemm<256,  64, false, false>(A1, A0, w5, 256, b5, nullptr, 0.f,  Wb, tx, ty, tid);

    // out[t][b][o][p0+p], result in A0 as [o][p].
    for (int e = tid; e < TILE * 64; e += NTHR) {
        int p = e & 63, o = e >> 6;
        out[(size_t)((t * 2 + b) * 64 + o) * HW + p0 + p] = A0[o * LDA + p];
    }
}

extern "C" void kernel_launch(void* const* d_in, const int* in_sizes, int n_in,
                              void* d_out, int out_size) {
    const float* feat  = (const float*)d_in[0];
    const float* times = (const float*)d_in[1];
    const float* w0 = (const float*)d_in[2];
    const float* b0 = (const float*)d_in[3];
    const float* w1 = (const float*)d_in[4];
    const float* b1 = (const float*)d_in[5];
    const float* w2 = (const float*)d_in[6];
    const float* b2 = (const float*)d_in[7];
    const float* w3 = (const float*)d_in[8];
    const float* b3 = (const float*)d_in[9];
    const float* w4 = (const float*)d_in[10];
    const float* b4 = (const float*)d_in[11];
    const float* w5 = (const float*)d_in[12];
    const float* b5 = (const float*)d_in[13];
    float* out = (float*)d_out;

    const size_t smem_bytes = (size_t)(2 * 256 * LDA + 64 * LDW) * sizeof(float); // 200960 B
    cudaFuncSetAttribute(liif_siren_kernel,
                         cudaFuncAttributeMaxDynamicSharedMemorySize, (int)smem_bytes);

    dim3 grid(HW / TILE, 2, 3);   // 5760 blocks
    dim3 block(32, 16, 1);
    liif_siren_kernel<<<grid, block, smem_bytes>>>(
        feat, times, w0, b0, w1, b1, w2, b2, w3, b3, w4, b4, w5, b5, out);
}